// round 2
// baseline (speedup 1.0000x reference)
#include <cuda_runtime.h>

// PointConv2d fused kernel, fp32 CUDA-core version (round 1).
// B=8, N=16384, K=9, C=64 -> CIN=66, O=9, CO=64, FAN=594.

namespace {
constexpr int B_   = 8;
constexpr int N_   = 16384;
constexpr int K_   = 9;
constexpr int CF_  = 64;    // feature channels
constexpr int CIN_ = 66;    // C + 2
constexpr int O_   = 9;     // weightnet outputs
constexpr int CO_  = 64;    // output channels
constexpr int FAN_ = 594;   // O_ * CIN_

constexpr int TN      = 32;   // points per block
constexpr int THREADS = 256;
constexpr int FCH     = 64;   // L chunk along fan dim
constexpr int LPAD    = 68;   // padded row stride for L_s (4-aligned, conflict-free)

// shared memory layout (floats)
constexpr int SM_PRM = 0;                 // 117 params, pad to 128
constexpr int SM_W   = 128;               // w_s[O_][K_][TN] = 2592
constexpr int SM_WF  = SM_W + O_ * K_ * TN;        // wf_s[FAN_][TN] = 19008
constexpr int SM_L   = SM_WF + FAN_ * TN;          // L_s[FCH][LPAD] = 4352
constexpr int SM_TOT = SM_L + FCH * LPAD;          // total floats = 26080
}

__device__ __forceinline__ float leaky(float x) { return fmaxf(x, 0.1f * x); }

__global__ __launch_bounds__(THREADS, 2)
void pointconv_kernel(const float* __restrict__ xy,     // [B,2,N,K]
                      const float* __restrict__ knnf,   // [B,CF,N,K]
                      const float* __restrict__ w1,     // [9,2]
                      const float* __restrict__ b1,     // [9]
                      const float* __restrict__ w2,     // [9,9]
                      const float* __restrict__ b2,     // [9]
                      const float* __restrict__ lw,     // [CO,FAN]
                      const float* __restrict__ lb,     // [CO]
                      float* __restrict__ out)          // [B,CO,N]
{
    extern __shared__ float sm[];
    float* prm  = sm + SM_PRM;
    float* w_s  = sm + SM_W;
    float* wf_s = sm + SM_WF;
    float* L_s  = sm + SM_L;

    const int t  = threadIdx.x;
    const int b  = blockIdx.y;
    const int n0 = blockIdx.x * TN;

    // ---- stage weightnet params into smem (117 floats) ----
    if (t < 18)            prm[t] = w1[t];
    else if (t < 27)       prm[t] = b1[t - 18];
    else if (t < 108)      prm[t] = w2[t - 27];
    else if (t < 117)      prm[t] = b2[t - 108];
    __syncthreads();
    const float* w1s = prm;
    const float* b1s = prm + 18;
    const float* w2s = prm + 27;
    const float* b2s = prm + 108;

    // ---- phase 1: WeightNet, one task per (point p, neighbor k) ----
    for (int task = t; task < TN * K_; task += THREADS) {
        const int p = task & (TN - 1);
        const int k = task >> 5;
        const int base = ((b * 2) * N_ + n0 + p) * K_ + k;
        const float x0 = xy[base];
        const float x1 = xy[base + N_ * K_];
        float h[O_];
#pragma unroll
        for (int j = 0; j < O_; j++) {
            float v = fmaf(w1s[j * 2], x0, fmaf(w1s[j * 2 + 1], x1, b1s[j]));
            h[j] = leaky(v);
        }
#pragma unroll
        for (int o = 0; o < O_; o++) {
            float v = b2s[o];
#pragma unroll
            for (int j = 0; j < O_; j++) v = fmaf(w2s[o * O_ + j], h[j], v);
            w_s[(o * K_ + k) * TN + p] = leaky(v);
        }
    }
    __syncthreads();

    // ---- phase 2: wf[o][c] per point, one task per (point p, channel c) ----
    for (int task = t; task < TN * CIN_; task += THREADS) {
        const int p = task & (TN - 1);
        const int c = task >> 5;
        const float* src;
        if (c < 2) src = xy   + ((b * 2  + c)       * N_ + n0 + p) * K_;
        else       src = knnf + ((b * CF_ + (c - 2)) * N_ + n0 + p) * K_;
        float f[K_];
#pragma unroll
        for (int k = 0; k < K_; k++) f[k] = src[k];
#pragma unroll
        for (int o = 0; o < O_; o++) {
            float v = 0.0f;
#pragma unroll
            for (int k = 0; k < K_; k++)
                v = fmaf(w_s[(o * K_ + k) * TN + p], f[k], v);
            wf_s[(o * CIN_ + c) * TN + p] = v;
        }
    }
    __syncthreads();

    // ---- phase 3: GEMM [TN=32 x CO=64] over FAN=594, chunked L in smem ----
    const int pg = t & 15;    // point pair: p = 2*pg, 2*pg+1
    const int cg = t >> 4;    // co quad:    co = 4*cg .. 4*cg+3
    float a00 = 0.f, a01 = 0.f, a02 = 0.f, a03 = 0.f;
    float a10 = 0.f, a11 = 0.f, a12 = 0.f, a13 = 0.f;

    for (int f0 = 0; f0 < FAN_; f0 += FCH) {
        const int cl = min(FCH, FAN_ - f0);
        // cooperative load of L chunk: L_s[fl][co] (transposed, padded)
        for (int idx = t; idx < cl * CO_; idx += THREADS) {
            const int co = idx / cl;
            const int fl = idx - co * cl;
            L_s[fl * LPAD + co] = lw[co * FAN_ + f0 + fl];
        }
        __syncthreads();
#pragma unroll 4
        for (int fl = 0; fl < cl; ++fl) {
            const float2 wv = *reinterpret_cast<const float2*>(
                &wf_s[(f0 + fl) * TN + (pg << 1)]);
            const float4 lv = *reinterpret_cast<const float4*>(
                &L_s[fl * LPAD + (cg << 2)]);
            a00 = fmaf(wv.x, lv.x, a00);
            a01 = fmaf(wv.x, lv.y, a01);
            a02 = fmaf(wv.x, lv.z, a02);
            a03 = fmaf(wv.x, lv.w, a03);
            a10 = fmaf(wv.y, lv.x, a10);
            a11 = fmaf(wv.y, lv.y, a11);
            a12 = fmaf(wv.y, lv.z, a12);
            a13 = fmaf(wv.y, lv.w, a13);
        }
        __syncthreads();
    }

    // ---- epilogue: bias + leaky, coalesced float2 stores ----
    const int n = n0 + (pg << 1);
    float acc0[4] = {a00, a01, a02, a03};
    float acc1[4] = {a10, a11, a12, a13};
#pragma unroll
    for (int j = 0; j < 4; j++) {
        const int co = (cg << 2) + j;
        const float bias = lb[co];
        float2 o2;
        o2.x = leaky(acc0[j] + bias);
        o2.y = leaky(acc1[j] + bias);
        *reinterpret_cast<float2*>(&out[(b * CO_ + co) * N_ + n]) = o2;
    }
}

extern "C" void kernel_launch(void* const* d_in, const int* in_sizes, int n_in,
                              void* d_out, int out_size)
{
    const float* xy   = (const float*)d_in[0];
    const float* knnf = (const float*)d_in[1];
    const float* w1   = (const float*)d_in[2];
    const float* b1   = (const float*)d_in[3];
    const float* w2   = (const float*)d_in[4];
    const float* b2   = (const float*)d_in[5];
    const float* lw   = (const float*)d_in[6];
    const float* lb   = (const float*)d_in[7];
    float* out = (float*)d_out;

    const size_t smem = SM_TOT * sizeof(float);  // 104320 bytes
    cudaFuncSetAttribute(pointconv_kernel,
                         cudaFuncAttributeMaxDynamicSharedMemorySize, (int)smem);

    dim3 grid(N_ / TN, B_);
    pointconv_kernel<<<grid, THREADS, smem>>>(xy, knnf, w1, b1, w2, b2, lw, lb, out);
}

// round 5
// speedup vs baseline: 3.0541x; 3.0541x over previous
#include <cuda_runtime.h>
#include <cuda_bf16.h>
#include <cstdint>

// PointConv2d fused (round 3): warp-level mma.sync bf16 3-term compensated GEMM.
// B=8, N=16384, K=9, C=64 -> CIN=66, O=9 (WeightNet), CO=64, FAN=594.
// GEMM k' = c*9 + o; chunks of 8 c = 72 slots, padded to 80 (5 k-steps of 16).

namespace {
constexpr int B_   = 8;
constexpr int N_   = 16384;
constexpr int K_   = 9;
constexpr int CF_  = 64;
constexpr int CIN_ = 66;
constexpr int O_   = 9;
constexpr int CO_  = 64;
constexpr int FAN_ = 594;

constexpr int TM      = 128;  // points per block (GEMM M)
constexpr int THREADS = 256;
constexpr int CPC     = 8;    // channels per chunk
constexpr int NCH     = 9;    // chunks (72 c; c>=66 are zero)
constexpr int SLOTS   = 80;   // padded k' slots per chunk (72 real)
constexpr int KSTEPS  = 5;    // 80 / 16

constexpr int BSTRIDE = 176;  // B smem row stride bytes (80*2=160 data + pad)
constexpr int ASTRIDE = 256;  // A smem row stride bytes ([slot][p] bf16, 128*2)

// shared memory byte offsets
constexpr int SM_PRM = 0;                       // 181 floats (724B) -> 768
constexpr int SM_BHI = 768;                     // 64*176 = 11264
constexpr int SM_BLO = SM_BHI + CO_ * BSTRIDE;  // 12032
constexpr int SM_A   = SM_BLO + CO_ * BSTRIDE;  // 23296 (also ws alias: 128*81*4)
constexpr int SM_AHI = SM_A;                    // 80*256 = 20480
constexpr int SM_ALO = SM_AHI + SLOTS * ASTRIDE;// 43776
constexpr int SM_END = SM_ALO + SLOTS * ASTRIDE;// 64256
constexpr int SM_WS_END = SM_A + TM * 81 * 4;   // 64768
constexpr int SM_TOT = (SM_WS_END > SM_END) ? SM_WS_END : SM_END;  // 64768
}

// prepacked reordered hi/lo-split linear weights: [chunk][co][88 slots(incl pad)]
__device__ __nv_bfloat16 g_Bhi[NCH * CO_ * 88];
__device__ __nv_bfloat16 g_Blo[NCH * CO_ * 88];

// ---------------- helpers ----------------
__device__ __forceinline__ uint32_t smem_u32(const void* p) {
    uint32_t a;
    asm("{ .reg .u64 t; cvta.to.shared.u64 t, %1; cvt.u32.u64 %0, t; }"
        : "=r"(a) : "l"(p));
    return a;
}
__device__ __forceinline__ uint64_t pack2(float lo, float hi) {
    uint64_t r;
    asm("mov.b64 %0, {%1, %2};" : "=l"(r) : "f"(lo), "f"(hi));
    return r;
}
__device__ __forceinline__ void unpack2(uint64_t v, float& a, float& b) {
    asm("mov.b64 {%0, %1}, %2;" : "=f"(a), "=f"(b) : "l"(v));
}
__device__ __forceinline__ uint64_t fma2(uint64_t a, uint64_t b, uint64_t c) {
    uint64_t r;
    asm("fma.rn.f32x2 %0, %1, %2, %3;" : "=l"(r) : "l"(a), "l"(b), "l"(c));
    return r;
}
__device__ __forceinline__ void ldsm_x4(uint32_t* r, uint32_t a) {
    asm volatile("ldmatrix.sync.aligned.m8n8.x4.shared.b16 {%0,%1,%2,%3}, [%4];"
        : "=r"(r[0]), "=r"(r[1]), "=r"(r[2]), "=r"(r[3]) : "r"(a));
}
__device__ __forceinline__ void ldsm_x4_t(uint32_t* r, uint32_t a) {
    asm volatile("ldmatrix.sync.aligned.m8n8.x4.trans.shared.b16 {%0,%1,%2,%3}, [%4];"
        : "=r"(r[0]), "=r"(r[1]), "=r"(r[2]), "=r"(r[3]) : "r"(a));
}
__device__ __forceinline__ void mma16816(float* d, const uint32_t* a,
                                         uint32_t b0, uint32_t b1) {
    asm volatile("mma.sync.aligned.m16n8k16.row.col.f32.bf16.bf16.f32 "
        "{%0,%1,%2,%3}, {%4,%5,%6,%7}, {%8,%9}, {%0,%1,%2,%3};"
        : "+f"(d[0]), "+f"(d[1]), "+f"(d[2]), "+f"(d[3])
        : "r"(a[0]), "r"(a[1]), "r"(a[2]), "r"(a[3]), "r"(b0), "r"(b1));
}
__device__ __forceinline__ float leaky(float x) { return fmaxf(x, 0.1f * x); }

// ---------------- prep: reorder + hi/lo split of lin_w ----------------
__global__ void pc_prep(const float* __restrict__ lw) {
    int idx = blockIdx.x * blockDim.x + threadIdx.x;
    if (idx >= NCH * CO_ * 88) return;
    const int kk = idx % 88;
    const int co = (idx / 88) % CO_;
    const int ck = idx / (88 * CO_);
    float v = 0.0f;
    if (kk < 72) {
        const int c = ck * CPC + kk / 9;
        const int o = kk % 9;
        if (c < CIN_) v = lw[co * FAN_ + o * CIN_ + c];
    }
    __nv_bfloat16 hi = __float2bfloat16(v);
    __nv_bfloat16 lo = __float2bfloat16(v - __bfloat162float(hi));
    g_Bhi[idx] = hi;
    g_Blo[idx] = lo;
}

// ---------------- main kernel ----------------
__global__ __launch_bounds__(THREADS, 2)
void pc_main(const float* __restrict__ xy,    // [B,2,N,K]
             const float* __restrict__ knnf,  // [B,64,N,K]
             const float* __restrict__ w1, const float* __restrict__ b1,
             const float* __restrict__ w2, const float* __restrict__ b2,
             const float* __restrict__ lb,    // [64]
             float* __restrict__ out)         // [B,64,N]
{
    extern __shared__ char smc[];
    const uint32_t sb = smem_u32(smc);
    float* prm = (float*)(smc + SM_PRM);
    float* ws  = (float*)(smc + SM_A);   // aliased with A tiles (ws dies first)

    const int t    = threadIdx.x;
    const int lane = t & 31;
    const int wid  = t >> 5;
    const int b    = blockIdx.y;
    const int n0   = blockIdx.x * TM;

    // stage params
    if (t < 18)        prm[t] = w1[t];
    else if (t < 27)   prm[t] = b1[t - 18];
    else if (t < 108)  prm[t] = w2[t - 27];
    else if (t < 117)  prm[t] = b2[t - 108];
    else if (t < 181)  prm[t] = lb[t - 117];
    __syncthreads();

    // ---- WeightNet: ws[p][o*9+k] ----
    for (int task = t; task < TM * K_; task += THREADS) {
        const int p2 = task & 127;
        const int k  = task >> 7;
        const size_t base = ((size_t)(2 * b) * N_ + n0 + p2) * K_ + k;
        const float x0 = xy[base];
        const float x1 = xy[base + (size_t)N_ * K_];
        float h[O_];
#pragma unroll
        for (int j = 0; j < O_; j++)
            h[j] = leaky(fmaf(prm[2 * j], x0, fmaf(prm[2 * j + 1], x1, prm[18 + j])));
#pragma unroll
        for (int o = 0; o < O_; o++) {
            float v = prm[108 + o];
#pragma unroll
            for (int j = 0; j < O_; j++) v = fmaf(prm[27 + o * O_ + j], h[j], v);
            ws[p2 * 81 + o * 9 + k] = leaky(v);
        }
    }
    __syncthreads();

    // ---- load this thread's w pairs into registers (f32x2 packed over o) ----
    const int p  = t & 127;       // point
    const int hh = t >> 7;        // o-half: 0 -> o0..3, 1 -> o4..8
    uint64_t wpA[9], wpB[9];
    float w8[9];
    {
        const float* wr = ws + p * 81;
        const int ob = hh * 36;   // hh0: o0..3 ; hh1: o4..7 (+ o8 scalar)
#pragma unroll
        for (int k = 0; k < 9; k++) {
            wpA[k] = pack2(wr[ob + k],      wr[ob + 9 + k]);
            wpB[k] = pack2(wr[ob + 18 + k], wr[ob + 27 + k]);
            w8[k]  = wr[72 + k];
        }
    }
    __syncthreads();

    // zero pad slots 72..79 of both A arrays (done once; never overwritten)
    {
        uint4 z = make_uint4(0, 0, 0, 0);
        char* padbase = (hh == 0) ? (smc + SM_AHI) : (smc + SM_ALO);
        ((uint4*)(padbase + 72 * ASTRIDE))[p] = z;   // 128 * 16B = 2048B per array
    }

    float acc[8][4];
#pragma unroll
    for (int j = 0; j < 8; j++)
#pragma unroll
        for (int q = 0; q < 4; q++) acc[j][q] = 0.0f;

    const uint32_t aAhi = sb + SM_AHI, aAlo = sb + SM_ALO;
    const uint32_t aBhi = sb + SM_BHI, aBlo = sb + SM_BLO;

#pragma unroll 1
    for (int ck = 0; ck < NCH; ck++) {
        // ---- stage B chunk (prepacked bf16 hi/lo) ----
        {
            const uint4* gh = (const uint4*)(g_Bhi + ck * (CO_ * 88));
            const uint4* gl = (const uint4*)(g_Blo + ck * (CO_ * 88));
            uint4* dh = (uint4*)(smc + SM_BHI);
            uint4* dl = (uint4*)(smc + SM_BLO);
            for (int i = t; i < 704; i += THREADS) { dh[i] = gh[i]; dl[i] = gl[i]; }
        }
        // ---- produce A chunk: wf values, hi/lo split, [slot][p] layout ----
#pragma unroll
        for (int ci = 0; ci < CPC; ci++) {
            const int c   = ck * CPC + ci;
            const int kk0 = ci * 9 + (hh ? 4 : 0);
            const int nv  = hh ? 5 : 4;
            float v[5];
            if (c < CIN_) {
                const float* src = (c < 2)
                    ? xy   + ((size_t)(2 * b + c) * N_ + n0 + p) * K_
                    : knnf + ((size_t)(CF_ * b + (c - 2)) * N_ + n0 + p) * K_;
                float f[9];
#pragma unroll
                for (int k = 0; k < 9; k++) f[k] = __ldg(src + k);
                uint64_t a0 = pack2(0.f, 0.f), a1 = pack2(0.f, 0.f);
                float s8 = 0.f;
#pragma unroll
                for (int k = 0; k < 9; k++) {
                    const uint64_t ff = pack2(f[k], f[k]);
                    a0 = fma2(ff, wpA[k], a0);
                    a1 = fma2(ff, wpB[k], a1);
                    if (hh) s8 = fmaf(f[k], w8[k], s8);
                }
                unpack2(a0, v[0], v[1]);
                unpack2(a1, v[2], v[3]);
                v[4] = s8;
            } else {
                v[0] = v[1] = v[2] = v[3] = v[4] = 0.f;
            }
#pragma unroll 5
            for (int j = 0; j < nv; j++) {
                const int kk = kk0 + j;
                const uint32_t off = (uint32_t)(kk * ASTRIDE) +
                    (((uint32_t)(p * 2)) ^ ((uint32_t)(kk & 7) << 4));
                __nv_bfloat16 hi = __float2bfloat16(v[j]);
                __nv_bfloat16 lo = __float2bfloat16(v[j] - __bfloat162float(hi));
                *(__nv_bfloat16*)(smc + SM_AHI + off) = hi;
                *(__nv_bfloat16*)(smc + SM_ALO + off) = lo;
            }
        }
        __syncthreads();

        // ---- mma: warp wid owns point rows [16*wid, 16*wid+16) ----
        {
            const int r  = lane & 7;
            const int tq = lane >> 3;
#pragma unroll
            for (int s = 0; s < KSTEPS; s++) {
                // A frags via ldmatrix.trans from [slot][p] storage
                const int krow = 16 * s + r + ((tq >> 1) << 3);
                const uint32_t mbyte = (uint32_t)((16 * wid + ((tq & 1) << 3)) * 2);
                const uint32_t aoff = (uint32_t)(krow * ASTRIDE) +
                                      (mbyte ^ ((uint32_t)(krow & 7) << 4));
                uint32_t ah[4], al[4];
                ldsm_x4_t(ah, aAhi + aoff);
                ldsm_x4_t(al, aAlo + aoff);
#pragma unroll
                for (int j = 0; j < 8; j += 2) {
                    const uint32_t boff =
                        (uint32_t)((8 * (j + (tq >> 1)) + r) * BSTRIDE +
                                   s * 32 + ((tq & 1) << 4));
                    uint32_t bh[4], bl[4];
                    ldsm_x4(bh, aBhi + boff);
                    ldsm_x4(bl, aBlo + boff);
                    mma16816(acc[j],     ah, bh[0], bh[1]);
                    mma16816(acc[j + 1], ah, bh[2], bh[3]);
                    mma16816(acc[j],     al, bh[0], bh[1]);
                    mma16816(acc[j + 1], al, bh[2], bh[3]);
                    mma16816(acc[j],     ah, bl[0], bl[1]);
                    mma16816(acc[j + 1], ah, bl[2], bl[3]);
                }
            }
        }
        __syncthreads();
    }

    // ---- epilogue: bias + leaky, direct stores ----
    {
        const int prow = 16 * wid + (lane >> 2);
        const int col2 = (lane & 3) * 2;
        const int n = n0 + prow;
#pragma unroll
        for (int j = 0; j < 8; j++) {
            const int co = 8 * j + col2;
            const float bi0 = prm[117 + co];
            const float bi1 = prm[117 + co + 1];
            float* o0 = out + (size_t)(b * CO_ + co) * N_ + n;
            float* o1 = out + (size_t)(b * CO_ + co + 1) * N_ + n;
            o0[0] = leaky(acc[j][0] + bi0);
            o1[0] = leaky(acc[j][1] + bi1);
            o0[8] = leaky(acc[j][2] + bi0);
            o1[8] = leaky(acc[j][3] + bi1);
        }
    }
}

extern "C" void kernel_launch(void* const* d_in, const int* in_sizes, int n_in,
                              void* d_out, int out_size)
{
    const float* xy   = (const float*)d_in[0];
    const float* knnf = (const float*)d_in[1];
    const float* w1   = (const float*)d_in[2];
    const float* b1   = (const float*)d_in[3];
    const float* w2   = (const float*)d_in[4];
    const float* b2   = (const float*)d_in[5];
    const float* lw   = (const float*)d_in[6];
    const float* lb   = (const float*)d_in[7];
    float* out = (float*)d_out;

    pc_prep<<<(NCH * CO_ * 88 + 255) / 256, 256>>>(lw);

    cudaFuncSetAttribute(pc_main, cudaFuncAttributeMaxDynamicSharedMemorySize, SM_TOT);
    dim3 grid(N_ / TM, B_);
    pc_main<<<grid, THREADS, SM_TOT>>>(xy, knnf, w1, b1, w2, b2, lb, out);
}

// round 9
// speedup vs baseline: 3.4858x; 1.1413x over previous
#include <cuda_runtime.h>
#include <cuda_bf16.h>
#include <cstdint>

// PointConv2d fused (round 4): mma.sync bf16 3-term GEMM + smem-staged features.
// B=8, N=16384, K=9, C=64 -> CIN=66, O=9, CO=64, FAN=594.

namespace {
constexpr int B_   = 8;
constexpr int N_   = 16384;
constexpr int K_   = 9;
constexpr int CF_  = 64;
constexpr int CIN_ = 66;
constexpr int O_   = 9;
constexpr int CO_  = 64;
constexpr int FAN_ = 594;

constexpr int TM      = 128;
constexpr int THREADS = 256;
constexpr int CPC     = 8;    // channels per chunk
constexpr int NCH     = 9;    // chunks
constexpr int SLOTS   = 80;   // padded k' slots per chunk
constexpr int KSTEPS  = 5;

constexpr int BSTRIDE = 176;  // B smem row stride bytes
constexpr int ASTRIDE = 256;  // A smem row stride bytes ([slot][p] bf16)

// shared memory byte offsets
constexpr int SM_PRM  = 0;                        // 181 floats -> 768
constexpr int SM_BHI  = 768;                      // 64*176 = 11264
constexpr int SM_BLO  = SM_BHI + CO_ * BSTRIDE;   // 12032
constexpr int SM_AHI  = SM_BLO + CO_ * BSTRIDE;   // 23296
constexpr int SM_ALO  = SM_AHI + SLOTS * ASTRIDE; // 43776
constexpr int SM_FEAT = SM_ALO + SLOTS * ASTRIDE; // 64256
constexpr int SM_TOT  = SM_FEAT + CPC * TM * K_ * 4;  // 64256+36864 = 101120
// ws alias: [SM_BHI .. SM_BHI+41472) — over B + part of A, both written later.
// epilogue transpose buffer alias: SM_AHI (64*132*4 = 33792 <= 40960).
}

// prepacked reordered hi/lo-split linear weights: [chunk][co][88]
__device__ __nv_bfloat16 g_Bhi[NCH * CO_ * 88];
__device__ __nv_bfloat16 g_Blo[NCH * CO_ * 88];

// ---------------- helpers ----------------
__device__ __forceinline__ uint32_t smem_u32(const void* p) {
    uint32_t a;
    asm("{ .reg .u64 t; cvta.to.shared.u64 t, %1; cvt.u32.u64 %0, t; }"
        : "=r"(a) : "l"(p));
    return a;
}
__device__ __forceinline__ uint64_t pack2(float lo, float hi) {
    uint64_t r;
    asm("mov.b64 %0, {%1, %2};" : "=l"(r) : "f"(lo), "f"(hi));
    return r;
}
__device__ __forceinline__ void unpack2(uint64_t v, float& a, float& b) {
    asm("mov.b64 {%0, %1}, %2;" : "=f"(a), "=f"(b) : "l"(v));
}
__device__ __forceinline__ uint64_t fma2(uint64_t a, uint64_t b, uint64_t c) {
    uint64_t r;
    asm("fma.rn.f32x2 %0, %1, %2, %3;" : "=l"(r) : "l"(a), "l"(b), "l"(c));
    return r;
}
__device__ __forceinline__ void ldsm_x4(uint32_t* r, uint32_t a) {
    asm volatile("ldmatrix.sync.aligned.m8n8.x4.shared.b16 {%0,%1,%2,%3}, [%4];"
        : "=r"(r[0]), "=r"(r[1]), "=r"(r[2]), "=r"(r[3]) : "r"(a));
}
__device__ __forceinline__ void ldsm_x4_t(uint32_t* r, uint32_t a) {
    asm volatile("ldmatrix.sync.aligned.m8n8.x4.trans.shared.b16 {%0,%1,%2,%3}, [%4];"
        : "=r"(r[0]), "=r"(r[1]), "=r"(r[2]), "=r"(r[3]) : "r"(a));
}
__device__ __forceinline__ void mma16816(float* d, const uint32_t* a,
                                         uint32_t b0, uint32_t b1) {
    asm volatile("mma.sync.aligned.m16n8k16.row.col.f32.bf16.bf16.f32 "
        "{%0,%1,%2,%3}, {%4,%5,%6,%7}, {%8,%9}, {%0,%1,%2,%3};"
        : "+f"(d[0]), "+f"(d[1]), "+f"(d[2]), "+f"(d[3])
        : "r"(a[0]), "r"(a[1]), "r"(a[2]), "r"(a[3]), "r"(b0), "r"(b1));
}
__device__ __forceinline__ float leaky(float x) { return fmaxf(x, 0.1f * x); }

// ---------------- prep: reorder + hi/lo split of lin_w ----------------
__global__ void pc_prep(const float* __restrict__ lw) {
    int idx = blockIdx.x * blockDim.x + threadIdx.x;
    if (idx >= NCH * CO_ * 88) return;
    const int kk = idx % 88;
    const int co = (idx / 88) % CO_;
    const int ck = idx / (88 * CO_);
    float v = 0.0f;
    if (kk < 72) {
        const int c = ck * CPC + kk / 9;
        const int o = kk % 9;
        if (c < CIN_) v = lw[co * FAN_ + o * CIN_ + c];
    }
    __nv_bfloat16 hi = __float2bfloat16(v);
    __nv_bfloat16 lo = __float2bfloat16(v - __bfloat162float(hi));
    g_Bhi[idx] = hi;
    g_Blo[idx] = lo;
}

// ---------------- main kernel ----------------
__global__ __launch_bounds__(THREADS, 2)
void pc_main(const float* __restrict__ xy,    // [B,2,N,K]
             const float* __restrict__ knnf,  // [B,64,N,K]
             const float* __restrict__ w1, const float* __restrict__ b1,
             const float* __restrict__ w2, const float* __restrict__ b2,
             const float* __restrict__ lb,    // [64]
             float* __restrict__ out)         // [B,64,N]
{
    extern __shared__ char smc[];
    const uint32_t sb = smem_u32(smc);
    float* prm   = (float*)(smc + SM_PRM);
    float* ws    = (float*)(smc + SM_BHI);   // alias over B+A (consumed first)
    float* featf = (float*)(smc + SM_FEAT);
    uint4* feat4 = (uint4*)(smc + SM_FEAT);

    const int t    = threadIdx.x;
    const int lane = t & 31;
    const int wid  = t >> 5;
    const int b    = blockIdx.y;
    const int n0   = blockIdx.x * TM;

    // stage params
    if (t < 18)        prm[t] = w1[t];
    else if (t < 27)   prm[t] = b1[t - 18];
    else if (t < 108)  prm[t] = w2[t - 27];
    else if (t < 117)  prm[t] = b2[t - 108];
    else if (t < 181)  prm[t] = lb[t - 117];

    // ---- feature staging helper (chunk ck -> feat buffer), coalesced uint4 ----
    // 8 channels x 128 pts x 9 k = 2304 uint4, 9 per thread.
    auto stage_feat = [&](int ck) {
#pragma unroll
        for (int j = 0; j < 9; j++) {
            const int idx = t + j * 256;
            const int cl  = idx / 288;
            const int rem = idx - cl * 288;
            const int c   = ck * CPC + cl;
            uint4 v = make_uint4(0, 0, 0, 0);
            if (c < CIN_) {
                const float* base = (c < 2)
                    ? xy   + ((size_t)(2 * b + c) * N_ + n0) * K_
                    : knnf + ((size_t)(CF_ * b + (c - 2)) * N_ + n0) * K_;
                v = ((const uint4*)base)[rem];
            }
            feat4[idx] = v;
        }
    };

    stage_feat(0);
    __syncthreads();

    // ---- WeightNet: ws[p][o*9+k], xy read from staged feat (c0, c1) ----
    for (int task = t; task < TM * K_; task += THREADS) {
        const int p2 = task & 127;
        const int k  = task >> 7;
        const float x0 = featf[p2 * K_ + k];
        const float x1 = featf[TM * K_ + p2 * K_ + k];
        float h[O_];
#pragma unroll
        for (int j = 0; j < O_; j++)
            h[j] = leaky(fmaf(prm[2 * j], x0, fmaf(prm[2 * j + 1], x1, prm[18 + j])));
#pragma unroll
        for (int o = 0; o < O_; o++) {
            float v = prm[108 + o];
#pragma unroll
            for (int j = 0; j < O_; j++) v = fmaf(prm[27 + o * O_ + j], h[j], v);
            ws[p2 * 81 + o * 9 + k] = leaky(v);
        }
    }
    __syncthreads();

    // ---- per-thread w pairs (f32x2 over o) ----
    const int p  = t & 127;
    const int hh = t >> 7;
    uint64_t wpA[9], wpB[9];
    float w8[9];
    {
        const float* wr = ws + p * 81;
        const int ob = hh * 36;
#pragma unroll
        for (int k = 0; k < 9; k++) {
            wpA[k] = pack2(wr[ob + k],      wr[ob + 9 + k]);
            wpB[k] = pack2(wr[ob + 18 + k], wr[ob + 27 + k]);
            w8[k]  = wr[72 + k];
        }
    }
    __syncthreads();

    // zero pad slots 72..79 of both A arrays (written once, after ws consumed)
    {
        uint4 z = make_uint4(0, 0, 0, 0);
        char* padbase = (hh == 0) ? (smc + SM_AHI) : (smc + SM_ALO);
        ((uint4*)(padbase + 72 * ASTRIDE))[p] = z;
    }

    float acc[8][4];
#pragma unroll
    for (int j = 0; j < 8; j++)
#pragma unroll
        for (int q = 0; q < 4; q++) acc[j][q] = 0.0f;

    const uint32_t aAhi = sb + SM_AHI, aAlo = sb + SM_ALO;
    const uint32_t aBhi = sb + SM_BHI, aBlo = sb + SM_BLO;

#pragma unroll 1
    for (int ck = 0; ck < NCH; ck++) {
        // ---- stage feat (except ck=0, already staged) + B chunk ----
        if (ck) stage_feat(ck);
        {
            const uint4* gh = (const uint4*)(g_Bhi + ck * (CO_ * 88));
            const uint4* gl = (const uint4*)(g_Blo + ck * (CO_ * 88));
            uint4* dh = (uint4*)(smc + SM_BHI);
            uint4* dl = (uint4*)(smc + SM_BLO);
            for (int i = t; i < 704; i += THREADS) { dh[i] = gh[i]; dl[i] = gl[i]; }
        }
        __syncthreads();

        // ---- produce A chunk from staged features ----
#pragma unroll
        for (int ci = 0; ci < CPC; ci++) {
            const int kk0 = ci * 9 + (hh ? 4 : 0);
            const int nv  = hh ? 5 : 4;
            const float* fp = featf + ci * (TM * K_) + p * K_;
            float f[9];
#pragma unroll
            for (int k = 0; k < 9; k++) f[k] = fp[k];
            float v[5];
            uint64_t a0 = pack2(0.f, 0.f), a1 = pack2(0.f, 0.f);
            float s8 = 0.f;
#pragma unroll
            for (int k = 0; k < 9; k++) {
                const uint64_t ff = pack2(f[k], f[k]);
                a0 = fma2(ff, wpA[k], a0);
                a1 = fma2(ff, wpB[k], a1);
                if (hh) s8 = fmaf(f[k], w8[k], s8);
            }
            unpack2(a0, v[0], v[1]);
            unpack2(a1, v[2], v[3]);
            v[4] = s8;
#pragma unroll 5
            for (int j = 0; j < nv; j++) {
                const int kk = kk0 + j;
                const uint32_t off = (uint32_t)(kk * ASTRIDE) +
                    (((uint32_t)(p * 2)) ^ ((uint32_t)(kk & 7) << 4));
                __nv_bfloat16 hi = __float2bfloat16(v[j]);
                __nv_bfloat16 lo = __float2bfloat16(v[j] - __bfloat162float(hi));
                *(__nv_bfloat16*)(smc + SM_AHI + off) = hi;
                *(__nv_bfloat16*)(smc + SM_ALO + off) = lo;
            }
        }
        __syncthreads();

        // ---- mma: warp wid owns point rows [16*wid, 16*wid+16) ----
        {
            const int r  = lane & 7;
            const int tq = lane >> 3;
#pragma unroll
            for (int s = 0; s < KSTEPS; s++) {
                const int krow = 16 * s + r + ((tq >> 1) << 3);
                const uint32_t mbyte = (uint32_t)((16 * wid + ((tq & 1) << 3)) * 2);
                const uint32_t aoff = (uint32_t)(krow * ASTRIDE) +
                                      (mbyte ^ ((uint32_t)(krow & 7) << 4));
                uint32_t ah[4], al[4];
                ldsm_x4_t(ah, aAhi + aoff);
                ldsm_x4_t(al, aAlo + aoff);
#pragma unroll
                for (int j = 0; j < 8; j += 2) {
                    const uint32_t boff =
                        (uint32_t)((8 * (j + (tq >> 1)) + r) * BSTRIDE +
                                   s * 32 + ((tq & 1) << 4));
                    uint32_t bh[4], bl[4];
                    ldsm_x4(bh, aBhi + boff);
                    ldsm_x4(bl, aBlo + boff);
                    mma16816(acc[j],     ah, bh[0], bh[1]);
                    mma16816(acc[j + 1], ah, bh[2], bh[3]);
                    mma16816(acc[j],     al, bh[0], bh[1]);
                    mma16816(acc[j + 1], al, bh[2], bh[3]);
                    mma16816(acc[j],     ah, bl[0], bl[1]);
                    mma16816(acc[j + 1], ah, bl[2], bl[3]);
                }
            }
        }
        __syncthreads();
    }

    // ---- epilogue: transpose through smem, coalesced float4 stores ----
    {
        float* tb = (float*)(smc + SM_AHI);   // [co][132] f32, conflict-free
        const int prow = 16 * wid + (lane >> 2);
        const int col2 = (lane & 3) * 2;
#pragma unroll
        for (int j = 0; j < 8; j++) {
            const int co = 8 * j + col2;
            tb[co * 132 + prow]           = acc[j][0];
            tb[(co + 1) * 132 + prow]     = acc[j][1];
            tb[co * 132 + prow + 8]       = acc[j][2];
            tb[(co + 1) * 132 + prow + 8] = acc[j][3];
        }
        __syncthreads();
#pragma unroll
        for (int j = 0; j < 8; j++) {
            const int i  = t + j * 256;
            const int co = i >> 5;
            const int u4 = i & 31;
            float4 v = *(float4*)(tb + co * 132 + u4 * 4);
            const float bi = prm[117 + co];
            v.x = leaky(v.x + bi);
            v.y = leaky(v.y + bi);
            v.z = leaky(v.z + bi);
            v.w = leaky(v.w + bi);
            *(float4*)(out + (size_t)(b * CO_ + co) * N_ + n0 + u4 * 4) = v;
        }
    }
}

extern "C" void kernel_launch(void* const* d_in, const int* in_sizes, int n_in,
                              void* d_out, int out_size)
{
    const float* xy   = (const float*)d_in[0];
    const float* knnf = (const float*)d_in[1];
    const float* w1   = (const float*)d_in[2];
    const float* b1   = (const float*)d_in[3];
    const float* w2   = (const float*)d_in[4];
    const float* b2   = (const float*)d_in[5];
    const float* lw   = (const float*)d_in[6];
    const float* lb   = (const float*)d_in[7];
    float* out = (float*)d_out;

    pc_prep<<<(NCH * CO_ * 88 + 255) / 256, 256>>>(lw);

    cudaFuncSetAttribute(pc_main, cudaFuncAttributeMaxDynamicSharedMemorySize, SM_TOT);
    dim3 grid(N_ / TM, B_);
    pc_main<<<grid, THREADS, SM_TOT>>>(xy, knnf, w1, b1, w2, b2, lb, out);
}